// round 1
// baseline (speedup 1.0000x reference)
#include <cuda_runtime.h>

#define B    16
#define C    32
#define T    16384
#define NL   30
#define OFF  3069
#define TOUT (T - OFF)   // 13315
#define NCH  256
#define TT2  32
#define TT3  16

// Scratch (device globals: allocation-free per harness rules)
__device__ float g_x[2][(size_t)B * C * T];          //  64 MB ping-pong residual stream
__device__ float g_h[(size_t)NL * B * C * T];        // ~1  GB per-layer gated outputs
__device__ float g_skip[(size_t)B * NCH * TOUT];     // 218 MB relu(skip-sum)

__device__ __forceinline__ float fast_tanh(float x) {
    // 1 - 2/(e^{2x}+1): saturates cleanly to +/-1, no NaN for |x| large
    return 1.f - 2.f / (__expf(2.f * x) + 1.f);
}
__device__ __forceinline__ float fast_sig(float x) {
    return 1.f / (1.f + __expf(-x));
}

// ---------------------------------------------------------------------------
// 1x1 causal conv: x0[b][c][t] = cw[c]*y[b][t] + cb[c]
// ---------------------------------------------------------------------------
__global__ void causal_kernel(const float* __restrict__ y,
                              const float* __restrict__ cw,
                              const float* __restrict__ cb) {
    int idx = blockIdx.x * 256 + threadIdx.x;         // over B*C*T
    if (idx >= B * C * T) return;
    int t = idx & (T - 1);
    int c = (idx >> 14) & 31;
    int b = idx >> 19;
    g_x[0][idx] = cw[c] * y[b * T + t] + cb[c];
}

// ---------------------------------------------------------------------------
// One WaveNet layer: h = tanh(Wf*x)*sig(Wg*x)  (K=2, dilation d, tail-aligned)
//                    x_next = Wr*h + x ;  h stored to g_h[layer]
// Block: 256 thr, tile of 64 time steps for one batch element.
// ---------------------------------------------------------------------------
__global__ __launch_bounds__(256) void layer_kernel(
    const float* __restrict__ fw, const float* __restrict__ gw,
    const float* __restrict__ rw, int layer, int ping, int d, int lo) {
    __shared__ float s_fw[C * C * 2], s_gw[C * C * 2], s_rw[C * C];
    __shared__ float xs[C][64], xd[C][64], hs[C][64];

    const float* xin  = g_x[ping];
    float*       xout = g_x[ping ^ 1];
    float*       hout = g_h + (size_t)layer * B * C * T;

    int b   = blockIdx.y;
    int tid = threadIdx.x;
    int t0  = (lo & ~63) + blockIdx.x * 64;           // 64-aligned tile start

    for (int i = tid; i < C * C * 2; i += 256) { s_fw[i] = fw[i]; s_gw[i] = gw[i]; }
    for (int i = tid; i < C * C;     i += 256) s_rw[i] = rw[i];

    const float* xb = xin + (size_t)b * C * T;
    for (int i = tid; i < C * 64; i += 256) {
        int c = i >> 6, tt = i & 63;
        int t = t0 + tt;
        bool v = (t >= lo) && (t < T);
        xs[c][tt] = v ? xb[c * T + t]     : 0.f;
        xd[c][tt] = v ? xb[c * T + t - d] : 0.f;
    }
    __syncthreads();

    // ---- phase 1: each thread computes one out-channel c over 8 time steps
    int c   = tid >> 3;
    int ttb = (tid & 7) * 8;
    float af[8], ag[8];
#pragma unroll
    for (int q = 0; q < 8; q++) { af[q] = 0.f; ag[q] = 0.f; }
#pragma unroll 8
    for (int ci = 0; ci < C; ci++) {
        float2 wf = *(const float2*)&s_fw[(c * C + ci) * 2];
        float2 wg = *(const float2*)&s_gw[(c * C + ci) * 2];
        float4 d0 = *(const float4*)&xd[ci][ttb];
        float4 d1 = *(const float4*)&xd[ci][ttb + 4];
        float4 c0 = *(const float4*)&xs[ci][ttb];
        float4 c1 = *(const float4*)&xs[ci][ttb + 4];
        float dv[8] = {d0.x, d0.y, d0.z, d0.w, d1.x, d1.y, d1.z, d1.w};
        float cv[8] = {c0.x, c0.y, c0.z, c0.w, c1.x, c1.y, c1.z, c1.w};
#pragma unroll
        for (int q = 0; q < 8; q++) {
            af[q] += wf.x * dv[q] + wf.y * cv[q];
            ag[q] += wg.x * dv[q] + wg.y * cv[q];
        }
    }
    float hv[8];
#pragma unroll
    for (int q = 0; q < 8; q++) hv[q] = fast_tanh(af[q]) * fast_sig(ag[q]);
#pragma unroll
    for (int q = 0; q < 8; q++) hs[c][ttb + q] = hv[q];
    {
        float* hob = hout + (size_t)b * C * T + (size_t)c * T;
#pragma unroll
        for (int q = 0; q < 8; q++) {
            int t = t0 + ttb + q;
            if (t >= lo && t < T) hob[t] = hv[q];
        }
    }
    __syncthreads();

    // ---- phase 2: residual 1x1 conv; thread = (group of 8 out-ch, 1 t)
    int grp = tid >> 6, tloc = tid & 63;
    float hreg[C];
#pragma unroll
    for (int ci = 0; ci < C; ci++) hreg[ci] = hs[ci][tloc];
    int tg = t0 + tloc;
    if (tg >= lo && tg < T) {
        float* xob = xout + (size_t)b * C * T;
#pragma unroll
        for (int k = 0; k < 8; k++) {
            int co = grp * 8 + k;
            float acc = 0.f;
#pragma unroll
            for (int ci = 0; ci < C; ci++) acc += s_rw[co * C + ci] * hreg[ci];
            xob[co * T + tg] = acc + xs[co][tloc];
        }
    }
}

// ---------------------------------------------------------------------------
// Fused skip reduction: skip[b][co][j] = relu( sum_{i,c} Wsk[i][co][c]*h_i[c][t] )
// for t = OFF + j (all 30 layers valid there). 256 thr = 256 out-ch,
// 32-t tile of all 960 h-channels in dynamic smem (120 KB).
// ---------------------------------------------------------------------------
__global__ __launch_bounds__(256) void skip_kernel(const float* __restrict__ wsk) {
    extern __shared__ float hs2[];                    // [NL*C][TT2]
    int b = blockIdx.y, j0 = blockIdx.x * TT2, tid = threadIdx.x;

    for (int i = tid; i < NL * C * TT2; i += 256) {
        int k = i >> 5, tt = i & (TT2 - 1);
        int j = j0 + tt;
        float v = 0.f;
        if (j < TOUT) {
            int layer = k >> 5, cc = k & 31;
            v = g_h[(((size_t)layer * B + b) * C + cc) * T + OFF + j];
        }
        hs2[i] = v;
    }
    __syncthreads();

    int co = tid;
    float acc[TT2];
#pragma unroll
    for (int q = 0; q < TT2; q++) acc[q] = 0.f;

    for (int layer = 0; layer < NL; layer++) {
        const float* wl = wsk + ((size_t)layer * NCH + co) * C;
#pragma unroll 4
        for (int c2 = 0; c2 < C; c2++) {
            float w = __ldg(&wl[c2]);
            const float4* hp = (const float4*)&hs2[(layer * C + c2) * TT2];
#pragma unroll
            for (int q4 = 0; q4 < TT2 / 4; q4++) {
                float4 h4 = hp[q4];
                acc[q4 * 4 + 0] += w * h4.x;
                acc[q4 * 4 + 1] += w * h4.y;
                acc[q4 * 4 + 2] += w * h4.z;
                acc[q4 * 4 + 3] += w * h4.w;
            }
        }
    }
    float* so = g_skip + ((size_t)b * NCH + co) * TOUT;
#pragma unroll
    for (int q = 0; q < TT2; q++)
        if (j0 + q < TOUT) so[j0 + q] = fmaxf(acc[q], 0.f);
}

// ---------------------------------------------------------------------------
// Head: out = W2 * relu(W1 * relu_skip + b1) + b2  (two 256x256 1x1 convs)
// ---------------------------------------------------------------------------
__global__ __launch_bounds__(256) void head_kernel(
    const float* __restrict__ w1, const float* __restrict__ b1,
    const float* __restrict__ w2, const float* __restrict__ b2,
    float* __restrict__ out) {
    __shared__ float ss[NCH * TT3];                   // 16 KB relu(skip) tile
    __shared__ float as[NCH * TT3];                   // 16 KB hidden tile
    int b = blockIdx.y, j0 = blockIdx.x * TT3, tid = threadIdx.x;

    for (int i = tid; i < NCH * TT3; i += 256) {
        int k = i >> 4, tt = i & (TT3 - 1);
        int j = j0 + tt;
        ss[i] = (j < TOUT) ? g_skip[((size_t)b * NCH + k) * TOUT + j] : 0.f;
    }
    __syncthreads();

    int co = tid;
    float acc[TT3];
#pragma unroll
    for (int q = 0; q < TT3; q++) acc[q] = 0.f;
    const float* w1r = w1 + co * NCH;
    for (int k = 0; k < NCH; k++) {
        float w = __ldg(&w1r[k]);
        const float4* sp = (const float4*)&ss[k * TT3];
#pragma unroll
        for (int q4 = 0; q4 < TT3 / 4; q4++) {
            float4 s4 = sp[q4];
            acc[q4 * 4 + 0] += w * s4.x;
            acc[q4 * 4 + 1] += w * s4.y;
            acc[q4 * 4 + 2] += w * s4.z;
            acc[q4 * 4 + 3] += w * s4.w;
        }
    }
    float bb1 = b1[co];
#pragma unroll
    for (int q = 0; q < TT3; q++) as[co * TT3 + q] = fmaxf(acc[q] + bb1, 0.f);
    __syncthreads();

#pragma unroll
    for (int q = 0; q < TT3; q++) acc[q] = 0.f;
    const float* w2r = w2 + co * NCH;
    for (int k = 0; k < NCH; k++) {
        float w = __ldg(&w2r[k]);
        const float4* sp = (const float4*)&as[k * TT3];
#pragma unroll
        for (int q4 = 0; q4 < TT3 / 4; q4++) {
            float4 s4 = sp[q4];
            acc[q4 * 4 + 0] += w * s4.x;
            acc[q4 * 4 + 1] += w * s4.y;
            acc[q4 * 4 + 2] += w * s4.z;
            acc[q4 * 4 + 3] += w * s4.w;
        }
    }
    float bb2 = b2[co];
    float* op = out + ((size_t)b * NCH + co) * TOUT;
#pragma unroll
    for (int q = 0; q < TT3; q++)
        if (j0 + q < TOUT) op[j0 + q] = acc[q] + bb2;
}

// ---------------------------------------------------------------------------
extern "C" void kernel_launch(void* const* d_in, const int* in_sizes, int n_in,
                              void* d_out, int out_size) {
    const float* y   = (const float*)d_in[0];
    const float* cw  = (const float*)d_in[1];
    const float* cb  = (const float*)d_in[2];
    const float* fw  = (const float*)d_in[3];
    const float* gw  = (const float*)d_in[4];
    const float* rw  = (const float*)d_in[5];
    const float* sw  = (const float*)d_in[6];
    const float* e1w = (const float*)d_in[7];
    const float* e1b = (const float*)d_in[8];
    const float* e2w = (const float*)d_in[9];
    const float* e2b = (const float*)d_in[10];
    float* out = (float*)d_out;

    causal_kernel<<<(B * C * T + 255) / 256, 256>>>(y, cw, cb);

    int lin = 0;
    for (int i = 0; i < NL; i++) {
        int d  = 1 << (i % 10);
        int lo = lin + d;                  // first valid output time index
        int tb = lo & ~63;
        int tiles = (T - tb + 63) / 64;
        dim3 grid(tiles, B);
        layer_kernel<<<grid, 256>>>(fw + (size_t)i * C * C * 2,
                                    gw + (size_t)i * C * C * 2,
                                    rw + (size_t)i * C * C,
                                    i, i & 1, d, lo);
        lin = lo;
    }

    cudaFuncSetAttribute(skip_kernel, cudaFuncAttributeMaxDynamicSharedMemorySize,
                         NL * C * TT2 * 4);
    dim3 gs((TOUT + TT2 - 1) / TT2, B);
    skip_kernel<<<gs, 256, NL * C * TT2 * 4>>>(sw);

    dim3 gh((TOUT + TT3 - 1) / TT3, B);
    head_kernel<<<gh, 256>>>(e1w, e1b, e2w, e2b, out);
}

// round 6
// speedup vs baseline: 1.8157x; 1.8157x over previous
#include <cuda_runtime.h>

#define B    16
#define C    32
#define T    16384
#define NL   30
#define OFF  3069
#define TOUT (T - OFF)   // 13315
#define NCH  256
#define TT2  32
#define TT3  16

// Scratch (device globals: allocation-free per harness rules)
__device__ float g_x[2][(size_t)B * C * T];          //  64 MB ping-pong residual stream
__device__ float g_h[(size_t)NL * B * C * T];        // ~1  GB per-layer gated outputs
__device__ float g_skip[(size_t)B * NCH * TOUT];     // 218 MB relu(skip-sum)
__device__ float g_swT[(size_t)NL * C * NCH];        // skip_w transposed [l*C+c][co]
__device__ float g_w1T[(size_t)NCH * NCH];           // end1_w transposed [k][co]
__device__ float g_w2T[(size_t)NCH * NCH];           // end2_w transposed [k][co]

__device__ __forceinline__ float fast_tanh(float x) {
    // 1 - 2/(e^{2x}+1): saturates cleanly to +/-1, no NaN for |x| large
    return 1.f - 2.f / (__expf(2.f * x) + 1.f);
}
__device__ __forceinline__ float fast_sig(float x) {
    return 1.f / (1.f + __expf(-x));
}

// ---------------------------------------------------------------------------
// Weight transposes (one-shot, trivial)
// ---------------------------------------------------------------------------
__global__ void transpose_sw_kernel(const float* __restrict__ sw) {
    int idx = blockIdx.x * 256 + threadIdx.x;        // over NL*NCH*C, sw[l][co][c]
    if (idx >= NL * NCH * C) return;
    int c  = idx & 31;
    int co = (idx >> 5) & 255;
    int l  = idx >> 13;
    g_swT[((size_t)l * C + c) * NCH + co] = sw[idx];
}

__global__ void transpose_w_kernel(const float* __restrict__ w, int which) {
    int idx = blockIdx.x * 256 + threadIdx.x;        // over NCH*NCH, w[co][k]
    if (idx >= NCH * NCH) return;
    int k  = idx & 255;
    int co = idx >> 8;
    float* dst = which ? g_w2T : g_w1T;
    dst[(size_t)k * NCH + co] = w[idx];
}

// ---------------------------------------------------------------------------
// 1x1 causal conv: x0[b][c][t] = cw[c]*y[b][t] + cb[c]
// ---------------------------------------------------------------------------
__global__ void causal_kernel(const float* __restrict__ y,
                              const float* __restrict__ cw,
                              const float* __restrict__ cb) {
    int idx = blockIdx.x * 256 + threadIdx.x;         // over B*C*T
    if (idx >= B * C * T) return;
    int t = idx & (T - 1);
    int c = (idx >> 14) & 31;
    int b = idx >> 19;
    g_x[0][idx] = cw[c] * y[b * T + t] + cb[c];
}

// ---------------------------------------------------------------------------
// One WaveNet layer (identical to the R1-proven version).
// ---------------------------------------------------------------------------
__global__ __launch_bounds__(256) void layer_kernel(
    const float* __restrict__ fw, const float* __restrict__ gw,
    const float* __restrict__ rw, int layer, int ping, int d, int lo) {
    __shared__ float s_fw[C * C * 2], s_gw[C * C * 2], s_rw[C * C];
    __shared__ float xs[C][64], xd[C][64], hs[C][64];

    const float* xin  = g_x[ping];
    float*       xout = g_x[ping ^ 1];
    float*       hout = g_h + (size_t)layer * B * C * T;

    int b   = blockIdx.y;
    int tid = threadIdx.x;
    int t0  = (lo & ~63) + blockIdx.x * 64;           // 64-aligned tile start

    for (int i = tid; i < C * C * 2; i += 256) { s_fw[i] = fw[i]; s_gw[i] = gw[i]; }
    for (int i = tid; i < C * C;     i += 256) s_rw[i] = rw[i];

    const float* xb = xin + (size_t)b * C * T;
    for (int i = tid; i < C * 64; i += 256) {
        int c = i >> 6, tt = i & 63;
        int t = t0 + tt;
        bool v = (t >= lo) && (t < T);
        xs[c][tt] = v ? xb[c * T + t]     : 0.f;
        xd[c][tt] = v ? xb[c * T + t - d] : 0.f;
    }
    __syncthreads();

    // ---- phase 1: each thread computes one out-channel c over 8 time steps
    int c   = tid >> 3;
    int ttb = (tid & 7) * 8;
    float af[8], ag[8];
#pragma unroll
    for (int q = 0; q < 8; q++) { af[q] = 0.f; ag[q] = 0.f; }
#pragma unroll 8
    for (int ci = 0; ci < C; ci++) {
        float2 wf = *(const float2*)&s_fw[(c * C + ci) * 2];
        float2 wg = *(const float2*)&s_gw[(c * C + ci) * 2];
        float4 d0 = *(const float4*)&xd[ci][ttb];
        float4 d1 = *(const float4*)&xd[ci][ttb + 4];
        float4 c0 = *(const float4*)&xs[ci][ttb];
        float4 c1 = *(const float4*)&xs[ci][ttb + 4];
        float dv[8] = {d0.x, d0.y, d0.z, d0.w, d1.x, d1.y, d1.z, d1.w};
        float cv[8] = {c0.x, c0.y, c0.z, c0.w, c1.x, c1.y, c1.z, c1.w};
#pragma unroll
        for (int q = 0; q < 8; q++) {
            af[q] += wf.x * dv[q] + wf.y * cv[q];
            ag[q] += wg.x * dv[q] + wg.y * cv[q];
        }
    }
    float hv[8];
#pragma unroll
    for (int q = 0; q < 8; q++) hv[q] = fast_tanh(af[q]) * fast_sig(ag[q]);
#pragma unroll
    for (int q = 0; q < 8; q++) hs[c][ttb + q] = hv[q];
    {
        float* hob = hout + (size_t)b * C * T + (size_t)c * T;
#pragma unroll
        for (int q = 0; q < 8; q++) {
            int t = t0 + ttb + q;
            if (t >= lo && t < T) hob[t] = hv[q];
        }
    }
    __syncthreads();

    // ---- phase 2: residual 1x1 conv; thread = (group of 8 out-ch, 1 t)
    int grp = tid >> 6, tloc = tid & 63;
    float hreg[C];
#pragma unroll
    for (int ci = 0; ci < C; ci++) hreg[ci] = hs[ci][tloc];
    int tg = t0 + tloc;
    if (tg >= lo && tg < T) {
        float* xob = xout + (size_t)b * C * T;
#pragma unroll
        for (int k = 0; k < 8; k++) {
            int co = grp * 8 + k;
            float acc = 0.f;
#pragma unroll
            for (int ci = 0; ci < C; ci++) acc += s_rw[co * C + ci] * hreg[ci];
            xob[co * T + tg] = acc + xs[co][tloc];
        }
    }
}

// ---------------------------------------------------------------------------
// Fused skip reduction (R1 structure; weights now read COALESCED from g_swT):
// skip[b][co][j] = relu( sum_{l,c} WskT[l*C+c][co] * h_l[c][OFF+j] )
// 256 thr = 256 out-ch, 32-t tile of all 960 h-channels in 120KB dyn smem.
// ---------------------------------------------------------------------------
__global__ __launch_bounds__(256) void skip_kernel() {
    extern __shared__ float hs2[];                    // [NL*C][TT2]
    int b = blockIdx.y, j0 = blockIdx.x * TT2, tid = threadIdx.x;

    for (int i = tid; i < NL * C * TT2; i += 256) {
        int k = i >> 5, tt = i & (TT2 - 1);
        int j = j0 + tt;
        float v = 0.f;
        if (j < TOUT) {
            int layer = k >> 5, cc = k & 31;
            v = g_h[(((size_t)layer * B + b) * C + cc) * T + OFF + j];
        }
        hs2[i] = v;
    }
    __syncthreads();

    int co = tid;
    float acc[TT2];
#pragma unroll
    for (int q = 0; q < TT2; q++) acc[q] = 0.f;

    const float* wT = g_swT + co;                     // lane-coalesced base
#pragma unroll 4
    for (int kk = 0; kk < NL * C; kk++) {             // kk = layer*C + c2
        float w = __ldg(&wT[(size_t)kk * NCH]);
        const float4* hp = (const float4*)&hs2[kk * TT2];
#pragma unroll
        for (int q4 = 0; q4 < TT2 / 4; q4++) {
            float4 h4 = hp[q4];
            acc[q4 * 4 + 0] += w * h4.x;
            acc[q4 * 4 + 1] += w * h4.y;
            acc[q4 * 4 + 2] += w * h4.z;
            acc[q4 * 4 + 3] += w * h4.w;
        }
    }
    float* so = g_skip + ((size_t)b * NCH + co) * TOUT;
#pragma unroll
    for (int q = 0; q < TT2; q++)
        if (j0 + q < TOUT) so[j0 + q] = fmaxf(acc[q], 0.f);
}

// ---------------------------------------------------------------------------
// Head (R1 structure; weights read COALESCED from g_w1T/g_w2T):
// out = W2 * relu(W1 * relu_skip + b1) + b2
// ---------------------------------------------------------------------------
__global__ __launch_bounds__(256) void head_kernel(
    const float* __restrict__ b1, const float* __restrict__ b2,
    float* __restrict__ out) {
    __shared__ float ss[NCH * TT3];                   // 16 KB relu(skip) tile
    __shared__ float as[NCH * TT3];                   // 16 KB hidden tile
    int b = blockIdx.y, j0 = blockIdx.x * TT3, tid = threadIdx.x;

    for (int i = tid; i < NCH * TT3; i += 256) {
        int k = i >> 4, tt = i & (TT3 - 1);
        int j = j0 + tt;
        ss[i] = (j < TOUT) ? g_skip[((size_t)b * NCH + k) * TOUT + j] : 0.f;
    }
    __syncthreads();

    int co = tid;
    float acc[TT3];
#pragma unroll
    for (int q = 0; q < TT3; q++) acc[q] = 0.f;
    const float* w1c = g_w1T + co;
#pragma unroll 4
    for (int k = 0; k < NCH; k++) {
        float w = __ldg(&w1c[(size_t)k * NCH]);
        const float4* sp = (const float4*)&ss[k * TT3];
#pragma unroll
        for (int q4 = 0; q4 < TT3 / 4; q4++) {
            float4 s4 = sp[q4];
            acc[q4 * 4 + 0] += w * s4.x;
            acc[q4 * 4 + 1] += w * s4.y;
            acc[q4 * 4 + 2] += w * s4.z;
            acc[q4 * 4 + 3] += w * s4.w;
        }
    }
    float bb1 = b1[co];
#pragma unroll
    for (int q = 0; q < TT3; q++) as[co * TT3 + q] = fmaxf(acc[q] + bb1, 0.f);
    __syncthreads();

#pragma unroll
    for (int q = 0; q < TT3; q++) acc[q] = 0.f;
    const float* w2c = g_w2T + co;
#pragma unroll 4
    for (int k = 0; k < NCH; k++) {
        float w = __ldg(&w2c[(size_t)k * NCH]);
        const float4* sp = (const float4*)&as[k * TT3];
#pragma unroll
        for (int q4 = 0; q4 < TT3 / 4; q4++) {
            float4 s4 = sp[q4];
            acc[q4 * 4 + 0] += w * s4.x;
            acc[q4 * 4 + 1] += w * s4.y;
            acc[q4 * 4 + 2] += w * s4.z;
            acc[q4 * 4 + 3] += w * s4.w;
        }
    }
    float bb2 = b2[co];
    float* op = out + ((size_t)b * NCH + co) * TOUT;
#pragma unroll
    for (int q = 0; q < TT3; q++)
        if (j0 + q < TOUT) op[j0 + q] = acc[q] + bb2;
}

// ---------------------------------------------------------------------------
extern "C" void kernel_launch(void* const* d_in, const int* in_sizes, int n_in,
                              void* d_out, int out_size) {
    const float* y   = (const float*)d_in[0];
    const float* cw  = (const float*)d_in[1];
    const float* cb  = (const float*)d_in[2];
    const float* fw  = (const float*)d_in[3];
    const float* gw  = (const float*)d_in[4];
    const float* rw  = (const float*)d_in[5];
    const float* sw  = (const float*)d_in[6];
    const float* e1w = (const float*)d_in[7];
    const float* e1b = (const float*)d_in[8];
    const float* e2w = (const float*)d_in[9];
    const float* e2b = (const float*)d_in[10];
    float* out = (float*)d_out;

    transpose_sw_kernel<<<(NL * NCH * C + 255) / 256, 256>>>(sw);
    transpose_w_kernel<<<(NCH * NCH + 255) / 256, 256>>>(e1w, 0);
    transpose_w_kernel<<<(NCH * NCH + 255) / 256, 256>>>(e2w, 1);

    causal_kernel<<<(B * C * T + 255) / 256, 256>>>(y, cw, cb);

    int lin = 0;
    for (int i = 0; i < NL; i++) {
        int d  = 1 << (i % 10);
        int lo = lin + d;                  // first valid output time index
        int tb = lo & ~63;
        int tiles = (T - tb + 63) / 64;
        dim3 grid(tiles, B);
        layer_kernel<<<grid, 256>>>(fw + (size_t)i * C * C * 2,
                                    gw + (size_t)i * C * C * 2,
                                    rw + (size_t)i * C * C,
                                    i, i & 1, d, lo);
        lin = lo;
    }

    cudaFuncSetAttribute(skip_kernel, cudaFuncAttributeMaxDynamicSharedMemorySize,
                         NL * C * TT2 * 4);
    dim3 gs((TOUT + TT2 - 1) / TT2, B);
    skip_kernel<<<gs, 256, NL * C * TT2 * 4>>>();

    dim3 gh((TOUT + TT3 - 1) / TT3, B);
    head_kernel<<<gh, 256>>>(e1b, e2b, out);
}

// round 7
// speedup vs baseline: 2.0066x; 1.1051x over previous
#include <cuda_runtime.h>

#define B    16
#define C    32
#define T    16384
#define NL   30
#define OFF  3069
#define TOUT (T - OFF)   // 13315
#define NCH  256
#define TT2  32
#define TT3  16
#define LT   128         // layer time tile

// Scratch (device globals: allocation-free per harness rules)
__device__ float g_x[2][(size_t)B * C * T];          //  64 MB ping-pong residual stream
__device__ float g_h[(size_t)NL * B * C * T];        // ~1  GB per-layer gated outputs
__device__ float g_skip[(size_t)B * NCH * TOUT];     // 218 MB relu(skip-sum)
__device__ float g_swT[(size_t)NL * C * NCH];        // skip_w transposed [l*C+c][co]
__device__ float g_w1T[(size_t)NCH * NCH];           // end1_w transposed [k][co]
__device__ float g_w2T[(size_t)NCH * NCH];           // end2_w transposed [k][co]

__device__ __forceinline__ float fast_tanh(float x) {
    // 1 - 2/(e^{2x}+1): saturates cleanly to +/-1, no NaN for |x| large
    return 1.f - 2.f / (__expf(2.f * x) + 1.f);
}
__device__ __forceinline__ float fast_sig(float x) {
    return 1.f / (1.f + __expf(-x));
}

// ---------------------------------------------------------------------------
// Weight transposes (one-shot, trivial)
// ---------------------------------------------------------------------------
__global__ void transpose_sw_kernel(const float* __restrict__ sw) {
    int idx = blockIdx.x * 256 + threadIdx.x;        // over NL*NCH*C, sw[l][co][c]
    if (idx >= NL * NCH * C) return;
    int c  = idx & 31;
    int co = (idx >> 5) & 255;
    int l  = idx >> 13;
    g_swT[((size_t)l * C + c) * NCH + co] = sw[idx];
}

__global__ void transpose_w_kernel(const float* __restrict__ w, int which) {
    int idx = blockIdx.x * 256 + threadIdx.x;        // over NCH*NCH, w[co][k]
    if (idx >= NCH * NCH) return;
    int k  = idx & 255;
    int co = idx >> 8;
    float* dst = which ? g_w2T : g_w1T;
    dst[(size_t)k * NCH + co] = w[idx];
}

// ---------------------------------------------------------------------------
// 1x1 causal conv: x0[b][c][t] = cw[c]*y[b][t] + cb[c]
// ---------------------------------------------------------------------------
__global__ void causal_kernel(const float* __restrict__ y,
                              const float* __restrict__ cw,
                              const float* __restrict__ cb) {
    int idx = blockIdx.x * 256 + threadIdx.x;         // over B*C*T
    if (idx >= B * C * T) return;
    int t = idx & (T - 1);
    int c = (idx >> 14) & 31;
    int b = idx >> 19;
    g_x[0][idx] = cw[c] * y[b * T + t] + cb[c];
}

// ---------------------------------------------------------------------------
// One WaveNet layer, 128-t tile, 256 threads.
// Phase 1: thread = (2 out-ch, 8 t). Phase 2: thread = (16 out-ch, 1 t).
// R1-style fully-unrolled register arrays (proven lmem-free construct).
// ---------------------------------------------------------------------------
__global__ __launch_bounds__(256) void layer_kernel(
    const float* __restrict__ fw, const float* __restrict__ gw,
    const float* __restrict__ rw, int layer, int ping, int d, int lo) {
    extern __shared__ float sm[];
    float* s_fw = sm;                                 // 2048
    float* s_gw = sm + 2048;                          // 2048
    float* s_rw = sm + 4096;                          // 1024
    float* xs   = sm + 5120;                          // C*LT
    float* xd   = xs + C * LT;                        // C*LT
    float* hs   = xd + C * LT;                        // C*LT

    const float* xin  = g_x[ping];
    float*       xout = g_x[ping ^ 1];
    float*       hout = g_h + (size_t)layer * B * C * T;

    int b   = blockIdx.y;
    int tid = threadIdx.x;
    int t0  = (lo & ~(LT - 1)) + blockIdx.x * LT;     // 128-aligned tile start

    for (int i = tid; i < C * C * 2; i += 256) { s_fw[i] = fw[i]; s_gw[i] = gw[i]; }
    for (int i = tid; i < C * C;     i += 256) s_rw[i] = rw[i];

    const float* xb = xin + (size_t)b * C * T;
    for (int i = tid; i < C * LT; i += 256) {
        int c = i >> 7, tt = i & (LT - 1);
        int t = t0 + tt;
        bool v = (t >= lo) && (t < T);
        xs[i] = v ? xb[c * T + t]     : 0.f;
        xd[i] = v ? xb[c * T + t - d] : 0.f;
    }
    __syncthreads();

    // ---- phase 1: thread = (channels c0,c1) x (8 time steps)
    int cp  = tid >> 4;                               // 0..15
    int c0  = cp * 2, c1 = c0 + 1;
    int ttb = (tid & 15) * 8;
    float af0[8], ag0[8], af1[8], ag1[8];
#pragma unroll
    for (int q = 0; q < 8; q++) { af0[q]=0.f; ag0[q]=0.f; af1[q]=0.f; ag1[q]=0.f; }
#pragma unroll 8
    for (int ci = 0; ci < C; ci++) {
        float2 wf0 = *(const float2*)&s_fw[(c0 * C + ci) * 2];
        float2 wf1 = *(const float2*)&s_fw[(c1 * C + ci) * 2];
        float2 wg0 = *(const float2*)&s_gw[(c0 * C + ci) * 2];
        float2 wg1 = *(const float2*)&s_gw[(c1 * C + ci) * 2];
        float4 d0 = *(const float4*)&xd[ci * LT + ttb];
        float4 d1 = *(const float4*)&xd[ci * LT + ttb + 4];
        float4 x0 = *(const float4*)&xs[ci * LT + ttb];
        float4 x1 = *(const float4*)&xs[ci * LT + ttb + 4];
        float dv[8] = {d0.x, d0.y, d0.z, d0.w, d1.x, d1.y, d1.z, d1.w};
        float cv[8] = {x0.x, x0.y, x0.z, x0.w, x1.x, x1.y, x1.z, x1.w};
#pragma unroll
        for (int q = 0; q < 8; q++) {
            af0[q] += wf0.x * dv[q] + wf0.y * cv[q];
            ag0[q] += wg0.x * dv[q] + wg0.y * cv[q];
            af1[q] += wf1.x * dv[q] + wf1.y * cv[q];
            ag1[q] += wg1.x * dv[q] + wg1.y * cv[q];
        }
    }
    float hv0[8], hv1[8];
#pragma unroll
    for (int q = 0; q < 8; q++) {
        hv0[q] = fast_tanh(af0[q]) * fast_sig(ag0[q]);
        hv1[q] = fast_tanh(af1[q]) * fast_sig(ag1[q]);
    }
#pragma unroll
    for (int q = 0; q < 8; q++) {
        hs[c0 * LT + ttb + q] = hv0[q];
        hs[c1 * LT + ttb + q] = hv1[q];
    }
    {
        // global h store only where skip reads it (t >= OFF)
        float* h0 = hout + (size_t)b * C * T + (size_t)c0 * T;
        float* h1 = hout + (size_t)b * C * T + (size_t)c1 * T;
#pragma unroll
        for (int q = 0; q < 8; q++) {
            int t = t0 + ttb + q;
            if (t >= OFF && t < T) { h0[t] = hv0[q]; h1[t] = hv1[q]; }
        }
    }
    __syncthreads();

    // ---- phase 2: residual 1x1 conv; thread = (group of 16 out-ch, 1 t)
    {
        int grp = tid >> 7, tloc = tid & (LT - 1);
        float hreg[C];
#pragma unroll
        for (int ci = 0; ci < C; ci++) hreg[ci] = hs[ci * LT + tloc];
        int tg = t0 + tloc;
        if (tg >= lo && tg < T) {
            float* xob = xout + (size_t)b * C * T;
#pragma unroll
            for (int k = 0; k < 16; k++) {
                int co = grp * 16 + k;
                float acc = 0.f;
#pragma unroll
                for (int ci = 0; ci < C; ci++) acc += s_rw[co * C + ci] * hreg[ci];
                xob[co * T + tg] = acc + xs[co * LT + tloc];
            }
        }
    }
}

// ---------------------------------------------------------------------------
// Fused skip reduction (weights coalesced via g_swT) — unchanged from R6.
// ---------------------------------------------------------------------------
__global__ __launch_bounds__(256) void skip_kernel() {
    extern __shared__ float hs2[];                    // [NL*C][TT2]
    int b = blockIdx.y, j0 = blockIdx.x * TT2, tid = threadIdx.x;

    for (int i = tid; i < NL * C * TT2; i += 256) {
        int k = i >> 5, tt = i & (TT2 - 1);
        int j = j0 + tt;
        float v = 0.f;
        if (j < TOUT) {
            int layer = k >> 5, cc = k & 31;
            v = g_h[(((size_t)layer * B + b) * C + cc) * T + OFF + j];
        }
        hs2[i] = v;
    }
    __syncthreads();

    int co = tid;
    float acc[TT2];
#pragma unroll
    for (int q = 0; q < TT2; q++) acc[q] = 0.f;

    const float* wT = g_swT + co;                     // lane-coalesced base
#pragma unroll 4
    for (int kk = 0; kk < NL * C; kk++) {             // kk = layer*C + c2
        float w = __ldg(&wT[(size_t)kk * NCH]);
        const float4* hp = (const float4*)&hs2[kk * TT2];
#pragma unroll
        for (int q4 = 0; q4 < TT2 / 4; q4++) {
            float4 h4 = hp[q4];
            acc[q4 * 4 + 0] += w * h4.x;
            acc[q4 * 4 + 1] += w * h4.y;
            acc[q4 * 4 + 2] += w * h4.z;
            acc[q4 * 4 + 3] += w * h4.w;
        }
    }
    float* so = g_skip + ((size_t)b * NCH + co) * TOUT;
#pragma unroll
    for (int q = 0; q < TT2; q++)
        if (j0 + q < TOUT) so[j0 + q] = fmaxf(acc[q], 0.f);
}

// ---------------------------------------------------------------------------
// Head (weights coalesced via g_w1T/g_w2T) — unchanged from R6.
// ---------------------------------------------------------------------------
__global__ __launch_bounds__(256) void head_kernel(
    const float* __restrict__ b1, const float* __restrict__ b2,
    float* __restrict__ out) {
    __shared__ float ss[NCH * TT3];                   // 16 KB relu(skip) tile
    __shared__ float as[NCH * TT3];                   // 16 KB hidden tile
    int b = blockIdx.y, j0 = blockIdx.x * TT3, tid = threadIdx.x;

    for (int i = tid; i < NCH * TT3; i += 256) {
        int k = i >> 4, tt = i & (TT3 - 1);
        int j = j0 + tt;
        ss[i] = (j < TOUT) ? g_skip[((size_t)b * NCH + k) * TOUT + j] : 0.f;
    }
    __syncthreads();

    int co = tid;
    float acc[TT3];
#pragma unroll
    for (int q = 0; q < TT3; q++) acc[q] = 0.f;
    const float* w1c = g_w1T + co;
#pragma unroll 4
    for (int k = 0; k < NCH; k++) {
        float w = __ldg(&w1c[(size_t)k * NCH]);
        const float4* sp = (const float4*)&ss[k * TT3];
#pragma unroll
        for (int q4 = 0; q4 < TT3 / 4; q4++) {
            float4 s4 = sp[q4];
            acc[q4 * 4 + 0] += w * s4.x;
            acc[q4 * 4 + 1] += w * s4.y;
            acc[q4 * 4 + 2] += w * s4.z;
            acc[q4 * 4 + 3] += w * s4.w;
        }
    }
    float bb1 = b1[co];
#pragma unroll
    for (int q = 0; q < TT3; q++) as[co * TT3 + q] = fmaxf(acc[q] + bb1, 0.f);
    __syncthreads();

#pragma unroll
    for (int q = 0; q < TT3; q++) acc[q] = 0.f;
    const float* w2c = g_w2T + co;
#pragma unroll 4
    for (int k = 0; k < NCH; k++) {
        float w = __ldg(&w2c[(size_t)k * NCH]);
        const float4* sp = (const float4*)&as[k * TT3];
#pragma unroll
        for (int q4 = 0; q4 < TT3 / 4; q4++) {
            float4 s4 = sp[q4];
            acc[q4 * 4 + 0] += w * s4.x;
            acc[q4 * 4 + 1] += w * s4.y;
            acc[q4 * 4 + 2] += w * s4.z;
            acc[q4 * 4 + 3] += w * s4.w;
        }
    }
    float bb2 = b2[co];
    float* op = out + ((size_t)b * NCH + co) * TOUT;
#pragma unroll
    for (int q = 0; q < TT3; q++)
        if (j0 + q < TOUT) op[j0 + q] = acc[q] + bb2;
}

// ---------------------------------------------------------------------------
extern "C" void kernel_launch(void* const* d_in, const int* in_sizes, int n_in,
                              void* d_out, int out_size) {
    const float* y   = (const float*)d_in[0];
    const float* cw  = (const float*)d_in[1];
    const float* cb  = (const float*)d_in[2];
    const float* fw  = (const float*)d_in[3];
    const float* gw  = (const float*)d_in[4];
    const float* rw  = (const float*)d_in[5];
    const float* sw  = (const float*)d_in[6];
    const float* e1w = (const float*)d_in[7];
    const float* e1b = (const float*)d_in[8];
    const float* e2w = (const float*)d_in[9];
    const float* e2b = (const float*)d_in[10];
    float* out = (float*)d_out;

    transpose_sw_kernel<<<(NL * NCH * C + 255) / 256, 256>>>(sw);
    transpose_w_kernel<<<(NCH * NCH + 255) / 256, 256>>>(e1w, 0);
    transpose_w_kernel<<<(NCH * NCH + 255) / 256, 256>>>(e2w, 1);

    causal_kernel<<<(B * C * T + 255) / 256, 256>>>(y, cw, cb);

    const int lyr_smem = (5120 + 3 * C * LT) * 4;     // 69,632 B
    cudaFuncSetAttribute(layer_kernel, cudaFuncAttributeMaxDynamicSharedMemorySize,
                         lyr_smem);

    int lin = 0;
    for (int i = 0; i < NL; i++) {
        int d  = 1 << (i % 10);
        int lo = lin + d;                  // first valid output time index
        int tb = lo & ~(LT - 1);
        int tiles = (T - tb + LT - 1) / LT;
        dim3 grid(tiles, B);
        layer_kernel<<<grid, 256, lyr_smem>>>(fw + (size_t)i * C * C * 2,
                                              gw + (size_t)i * C * C * 2,
                                              rw + (size_t)i * C * C,
                                              i, i & 1, d, lo);
        lin = lo;
    }

    cudaFuncSetAttribute(skip_kernel, cudaFuncAttributeMaxDynamicSharedMemorySize,
                         NL * C * TT2 * 4);
    dim3 gs((TOUT + TT2 - 1) / TT2, B);
    skip_kernel<<<gs, 256, NL * C * TT2 * 4>>>();

    dim3 gh((TOUT + TT3 - 1) / TT3, B);
    head_kernel<<<gh, 256>>>(e1b, e2b, out);
}

// round 8
// speedup vs baseline: 2.1296x; 1.0613x over previous
#include <cuda_runtime.h>

#define B    16
#define C    32
#define T    16384
#define NL   30
#define OFF  3069
#define TOUT (T - OFF)   // 13315
#define NCH  256
#define TT2  32
#define TT3  16
#define LT   128         // layer time tile

typedef unsigned long long u64;

// Packed f32x2 helpers (Blackwell): 2 fp32 FMAs per issue slot, .rn rounding
#define PACK2(dst, lo, hi) \
    asm("mov.b64 %0, {%1, %2};" : "=l"(dst) : "f"(lo), "f"(hi))
#define UNPACK2(lo, hi, src) \
    asm("mov.b64 {%0, %1}, %2;" : "=f"(lo), "=f"(hi) : "l"(src))
#define FMA2(acc, a, b) \
    asm("fma.rn.f32x2 %0, %1, %2, %0;" : "+l"(acc) : "l"(a), "l"(b))

// Scratch (device globals: allocation-free per harness rules)
__device__ float g_x[2][(size_t)B * C * T];          //  64 MB ping-pong residual stream
__device__ float g_h[(size_t)NL * B * C * T];        // ~1  GB per-layer gated outputs
__device__ float g_skip[(size_t)B * NCH * TOUT];     // 218 MB relu(skip-sum)
__device__ float g_swT[(size_t)NL * C * NCH];        // skip_w transposed [l*C+c][co]
__device__ float g_w1T[(size_t)NCH * NCH];           // end1_w transposed [k][co]
__device__ float g_w2T[(size_t)NCH * NCH];           // end2_w transposed [k][co]

__device__ __forceinline__ float fast_tanh(float x) {
    return 1.f - 2.f / (__expf(2.f * x) + 1.f);
}
__device__ __forceinline__ float fast_sig(float x) {
    return 1.f / (1.f + __expf(-x));
}

// ---------------------------------------------------------------------------
// Weight transposes (one-shot, trivial)
// ---------------------------------------------------------------------------
__global__ void transpose_sw_kernel(const float* __restrict__ sw) {
    int idx = blockIdx.x * 256 + threadIdx.x;        // over NL*NCH*C, sw[l][co][c]
    if (idx >= NL * NCH * C) return;
    int c  = idx & 31;
    int co = (idx >> 5) & 255;
    int l  = idx >> 13;
    g_swT[((size_t)l * C + c) * NCH + co] = sw[idx];
}

__global__ void transpose_w_kernel(const float* __restrict__ w, int which) {
    int idx = blockIdx.x * 256 + threadIdx.x;        // over NCH*NCH, w[co][k]
    if (idx >= NCH * NCH) return;
    int k  = idx & 255;
    int co = idx >> 8;
    float* dst = which ? g_w2T : g_w1T;
    dst[(size_t)k * NCH + co] = w[idx];
}

// ---------------------------------------------------------------------------
// 1x1 causal conv: x0[b][c][t] = cw[c]*y[b][t] + cb[c]
// ---------------------------------------------------------------------------
__global__ void causal_kernel(const float* __restrict__ y,
                              const float* __restrict__ cw,
                              const float* __restrict__ cb) {
    int idx = blockIdx.x * 256 + threadIdx.x;         // over B*C*T
    if (idx >= B * C * T) return;
    int t = idx & (T - 1);
    int c = (idx >> 14) & 31;
    int b = idx >> 19;
    g_x[0][idx] = cw[c] * y[b * T + t] + cb[c];
}

// ---------------------------------------------------------------------------
// One WaveNet layer, 128-t tile, 256 threads.
// Phase 1: thread = (2 out-ch, 8 t), f32x2-packed FMAs.
// Phase 2: thread = (16 out-ch, 1 t), scalar.
// ---------------------------------------------------------------------------
__global__ __launch_bounds__(256) void layer_kernel(
    const float* __restrict__ fw, const float* __restrict__ gw,
    const float* __restrict__ rw, int layer, int ping, int d, int lo) {
    extern __shared__ float sm[];
    float* s_fw = sm;                                 // 2048
    float* s_gw = sm + 2048;                          // 2048
    float* s_rw = sm + 4096;                          // 1024
    float* xs   = sm + 5120;                          // C*LT
    float* xd   = xs + C * LT;                        // C*LT
    float* hs   = xd + C * LT;                        // C*LT

    const float* xin  = g_x[ping];
    float*       xout = g_x[ping ^ 1];
    float*       hout = g_h + (size_t)layer * B * C * T;

    int b   = blockIdx.y;
    int tid = threadIdx.x;
    int t0  = (lo & ~(LT - 1)) + blockIdx.x * LT;     // 128-aligned tile start

    for (int i = tid; i < C * C * 2; i += 256) { s_fw[i] = fw[i]; s_gw[i] = gw[i]; }
    for (int i = tid; i < C * C;     i += 256) s_rw[i] = rw[i];

    const float* xb = xin + (size_t)b * C * T;
    for (int i = tid; i < C * LT; i += 256) {
        int c = i >> 7, tt = i & (LT - 1);
        int t = t0 + tt;
        bool v = (t >= lo) && (t < T);
        xs[i] = v ? xb[c * T + t]     : 0.f;
        xd[i] = v ? xb[c * T + t - d] : 0.f;
    }
    __syncthreads();

    // ---- phase 1: thread = (channels c0,c1) x (8 time steps), packed f32x2
    int cp  = tid >> 4;                               // 0..15
    int c0  = cp * 2, c1 = c0 + 1;
    int ttb = (tid & 15) * 8;
    u64 a_f0[4], a_g0[4], a_f1[4], a_g1[4];
#pragma unroll
    for (int q = 0; q < 4; q++) { a_f0[q]=0; a_g0[q]=0; a_f1[q]=0; a_g1[q]=0; }
#pragma unroll 8
    for (int ci = 0; ci < C; ci++) {
        float2 wf0 = *(const float2*)&s_fw[(c0 * C + ci) * 2];
        float2 wf1 = *(const float2*)&s_fw[(c1 * C + ci) * 2];
        float2 wg0 = *(const float2*)&s_gw[(c0 * C + ci) * 2];
        float2 wg1 = *(const float2*)&s_gw[(c1 * C + ci) * 2];
        u64 wf0x, wf0y, wg0x, wg0y, wf1x, wf1y, wg1x, wg1y;
        PACK2(wf0x, wf0.x, wf0.x);  PACK2(wf0y, wf0.y, wf0.y);
        PACK2(wg0x, wg0.x, wg0.x);  PACK2(wg0y, wg0.y, wg0.y);
        PACK2(wf1x, wf1.x, wf1.x);  PACK2(wf1y, wf1.y, wf1.y);
        PACK2(wg1x, wg1.x, wg1.x);  PACK2(wg1y, wg1.y, wg1.y);
        const u64* dp = (const u64*)&xd[ci * LT + ttb];
        const u64* sp = (const u64*)&xs[ci * LT + ttb];
#pragma unroll
        for (int q = 0; q < 4; q++) {
            u64 dv = dp[q], sv = sp[q];
            FMA2(a_f0[q], wf0x, dv);  FMA2(a_f0[q], wf0y, sv);
            FMA2(a_g0[q], wg0x, dv);  FMA2(a_g0[q], wg0y, sv);
            FMA2(a_f1[q], wf1x, dv);  FMA2(a_f1[q], wf1y, sv);
            FMA2(a_g1[q], wg1x, dv);  FMA2(a_g1[q], wg1y, sv);
        }
    }
    float af0[8], ag0[8], af1[8], ag1[8];
#pragma unroll
    for (int q = 0; q < 4; q++) {
        UNPACK2(af0[2*q], af0[2*q+1], a_f0[q]);
        UNPACK2(ag0[2*q], ag0[2*q+1], a_g0[q]);
        UNPACK2(af1[2*q], af1[2*q+1], a_f1[q]);
        UNPACK2(ag1[2*q], ag1[2*q+1], a_g1[q]);
    }
    float hv0[8], hv1[8];
#pragma unroll
    for (int q = 0; q < 8; q++) {
        hv0[q] = fast_tanh(af0[q]) * fast_sig(ag0[q]);
        hv1[q] = fast_tanh(af1[q]) * fast_sig(ag1[q]);
    }
#pragma unroll
    for (int q = 0; q < 8; q++) {
        hs[c0 * LT + ttb + q] = hv0[q];
        hs[c1 * LT + ttb + q] = hv1[q];
    }
    {
        // global h store only where skip reads it (t >= OFF)
        float* h0 = hout + (size_t)b * C * T + (size_t)c0 * T;
        float* h1 = hout + (size_t)b * C * T + (size_t)c1 * T;
#pragma unroll
        for (int q = 0; q < 8; q++) {
            int t = t0 + ttb + q;
            if (t >= OFF && t < T) { h0[t] = hv0[q]; h1[t] = hv1[q]; }
        }
    }
    __syncthreads();

    // ---- phase 2: residual 1x1 conv; thread = (group of 16 out-ch, 1 t)
    {
        int grp = tid >> 7, tloc = tid & (LT - 1);
        float hreg[C];
#pragma unroll
        for (int ci = 0; ci < C; ci++) hreg[ci] = hs[ci * LT + tloc];
        int tg = t0 + tloc;
        if (tg >= lo && tg < T) {
            float* xob = xout + (size_t)b * C * T;
#pragma unroll
            for (int k = 0; k < 16; k++) {
                int co = grp * 16 + k;
                float acc = 0.f;
#pragma unroll
                for (int ci = 0; ci < C; ci++) acc += s_rw[co * C + ci] * hreg[ci];
                xob[co * T + tg] = acc + xs[co * LT + tloc];
            }
        }
    }
}

// ---------------------------------------------------------------------------
// Fused skip reduction (coalesced g_swT weights), f32x2-packed accumulate.
// ---------------------------------------------------------------------------
__global__ __launch_bounds__(256) void skip_kernel() {
    extern __shared__ float hs2[];                    // [NL*C][TT2]
    int b = blockIdx.y, j0 = blockIdx.x * TT2, tid = threadIdx.x;

    for (int i = tid; i < NL * C * TT2; i += 256) {
        int k = i >> 5, tt = i & (TT2 - 1);
        int j = j0 + tt;
        float v = 0.f;
        if (j < TOUT) {
            int layer = k >> 5, cc = k & 31;
            v = g_h[(((size_t)layer * B + b) * C + cc) * T + OFF + j];
        }
        hs2[i] = v;
    }
    __syncthreads();

    int co = tid;
    u64 acc2[TT2 / 2];
#pragma unroll
    for (int q = 0; q < TT2 / 2; q++) acc2[q] = 0;

    const float* wT = g_swT + co;                     // lane-coalesced base
#pragma unroll 4
    for (int kk = 0; kk < NL * C; kk++) {             // kk = layer*C + c2
        float w = __ldg(&wT[(size_t)kk * NCH]);
        u64 w2;  PACK2(w2, w, w);
        const u64* hp = (const u64*)&hs2[kk * TT2];
#pragma unroll
        for (int q = 0; q < TT2 / 2; q++) FMA2(acc2[q], w2, hp[q]);
    }
    float* so = g_skip + ((size_t)b * NCH + co) * TOUT;
#pragma unroll
    for (int q = 0; q < TT2 / 2; q++) {
        float lo, hi;
        UNPACK2(lo, hi, acc2[q]);
        int j = j0 + 2 * q;
        if (j     < TOUT) so[j]     = fmaxf(lo, 0.f);
        if (j + 1 < TOUT) so[j + 1] = fmaxf(hi, 0.f);
    }
}

// ---------------------------------------------------------------------------
// Head (coalesced g_w1T/g_w2T), f32x2-packed accumulate.
// ---------------------------------------------------------------------------
__global__ __launch_bounds__(256) void head_kernel(
    const float* __restrict__ b1, const float* __restrict__ b2,
    float* __restrict__ out) {
    __shared__ float ss[NCH * TT3];                   // 16 KB relu(skip) tile
    __shared__ float as[NCH * TT3];                   // 16 KB hidden tile
    int b = blockIdx.y, j0 = blockIdx.x * TT3, tid = threadIdx.x;

    for (int i = tid; i < NCH * TT3; i += 256) {
        int k = i >> 4, tt = i & (TT3 - 1);
        int j = j0 + tt;
        ss[i] = (j < TOUT) ? g_skip[((size_t)b * NCH + k) * TOUT + j] : 0.f;
    }
    __syncthreads();

    int co = tid;
    u64 acc2[TT3 / 2];
#pragma unroll
    for (int q = 0; q < TT3 / 2; q++) acc2[q] = 0;
    const float* w1c = g_w1T + co;
#pragma unroll 4
    for (int k = 0; k < NCH; k++) {
        float w = __ldg(&w1c[(size_t)k * NCH]);
        u64 w2;  PACK2(w2, w, w);
        const u64* sp = (const u64*)&ss[k * TT3];
#pragma unroll
        for (int q = 0; q < TT3 / 2; q++) FMA2(acc2[q], w2, sp[q]);
    }
    float bb1 = b1[co];
#pragma unroll
    for (int q = 0; q < TT3 / 2; q++) {
        float lo, hi;
        UNPACK2(lo, hi, acc2[q]);
        as[co * TT3 + 2 * q]     = fmaxf(lo + bb1, 0.f);
        as[co * TT3 + 2 * q + 1] = fmaxf(hi + bb1, 0.f);
    }
    __syncthreads();

#pragma unroll
    for (int q = 0; q < TT3 / 2; q++) acc2[q] = 0;
    const float* w2c = g_w2T + co;
#pragma unroll 4
    for (int k = 0; k < NCH; k++) {
        float w = __ldg(&w2c[(size_t)k * NCH]);
        u64 w2;  PACK2(w2, w, w);
        const u64* sp = (const u64*)&as[k * TT3];
#pragma unroll
        for (int q = 0; q < TT3 / 2; q++) FMA2(acc2[q], w2, sp[q]);
    }
    float bb2 = b2[co];
    float* op = out + ((size_t)b * NCH + co) * TOUT;
#pragma unroll
    for (int q = 0; q < TT3 / 2; q++) {
        float lo, hi;
        UNPACK2(lo, hi, acc2[q]);
        int j = j0 + 2 * q;
        if (j     < TOUT) op[j]     = lo + bb2;
        if (j + 1 < TOUT) op[j + 1] = hi + bb2;
    }
}

// ---------------------------------------------------------------------------
extern "C" void kernel_launch(void* const* d_in, const int* in_sizes, int n_in,
                              void* d_out, int out_size) {
    const float* y   = (const float*)d_in[0];
    const float* cw  = (const float*)d_in[1];
    const float* cb  = (const float*)d_in[2];
    const float* fw  = (const float*)d_in[3];
    const float* gw  = (const float*)d_in[4];
    const float* rw  = (const float*)d_in[5];
    const float* sw  = (const float*)d_in[6];
    const float* e1w = (const float*)d_in[7];
    const float* e1b = (const float*)d_in[8];
    const float* e2w = (const float*)d_in[9];
    const float* e2b = (const float*)d_in[10];
    float* out = (float*)d_out;

    transpose_sw_kernel<<<(NL * NCH * C + 255) / 256, 256>>>(sw);
    transpose_w_kernel<<<(NCH * NCH + 255) / 256, 256>>>(e1w, 0);
    transpose_w_kernel<<<(NCH * NCH + 255) / 256, 256>>>(e2w, 1);

    causal_kernel<<<(B * C * T + 255) / 256, 256>>>(y, cw, cb);

    const int lyr_smem = (5120 + 3 * C * LT) * 4;     // 69,632 B
    cudaFuncSetAttribute(layer_kernel, cudaFuncAttributeMaxDynamicSharedMemorySize,
                         lyr_smem);

    int lin = 0;
    for (int i = 0; i < NL; i++) {
        int d  = 1 << (i % 10);
        int lo = lin + d;                  // first valid output time index
        int tb = lo & ~(LT - 1);
        int tiles = (T - tb + LT - 1) / LT;
        dim3 grid(tiles, B);
        layer_kernel<<<grid, 256, lyr_smem>>>(fw + (size_t)i * C * C * 2,
                                              gw + (size_t)i * C * C * 2,
                                              rw + (size_t)i * C * C,
                                              i, i & 1, d, lo);
        lin = lo;
    }

    cudaFuncSetAttribute(skip_kernel, cudaFuncAttributeMaxDynamicSharedMemorySize,
                         NL * C * TT2 * 4);
    dim3 gs((TOUT + TT2 - 1) / TT2, B);
    skip_kernel<<<gs, 256, NL * C * TT2 * 4>>>();

    dim3 gh((TOUT + TT3 - 1) / TT3, B);
    head_kernel<<<gh, 256>>>(e1b, e2b, out);
}